// round 3
// baseline (speedup 1.0000x reference)
#include <cuda_runtime.h>
#include <math.h>

// ---- problem constants ----
#define NBATCH 4
#define NATOMS 600
#define HALFN  300
#define NBINS  64
#define BIN_W      0.1171875f            // 7.5/64 (exact fp32)
#define CUT_ADJ    7.734375f             // 7.5 + 2*BIN_W (exact)
#define GW         (7.5f / 63.0f)        // Gaussian offset spacing == width
#define INV_GW     (63.0f / 7.5f)
#define GCOEFF     (-0.5f / (GW * GW))

// fine sub-histogram
#define NSUB       2048
#define SUBW       (CUT_ADJ / (float)NSUB)
#define INV_SUBW   ((float)NSUB / CUT_ADJ)
#define WIN2       6                     // +-6 bins in reconstruction: err ~ e^-21

// stage A launch shape
#define ABLK_X     148
#define A_BLOCKS   (ABLK_X * NBATCH)     // 592
#define TPB        256
#define PB_SPACE   (HALFN * NATOMS)      // 180000 balanced-triangle slots/batch

// stage B launch shape: 8 s-chunks x 8 b-slices
#define B_BLOCKS   64
#define B_SLICES   8

// static device scratch (no cudaMalloc allowed)
__device__ float        g_pn[A_BLOCKS * NSUB];   // per-block sub-hist counts
__device__ float        g_pm[A_BLOCKS * NSUB];   // per-block sub-hist first moments
__device__ float        g_bpart[B_BLOCKS * NBINS];
__device__ unsigned int g_done2 = 0;             // reset by last B block each run

// ---------------- Stage A: pair loop -> fine sub-histogram ----------------
__global__ void __launch_bounds__(TPB)
rdf_pairs_kernel(const float* __restrict__ xyz) {
    __shared__ float s_pos[NATOMS * 3];  // 7.2 KB
    __shared__ float s_n[NSUB];          // 8 KB
    __shared__ float s_m[NSUB];          // 8 KB

    const int t   = threadIdx.x;
    const int bat = blockIdx.y;

    const float* __restrict__ src = xyz + bat * NATOMS * 3;
    for (int k = t; k < NATOMS * 3; k += TPB) s_pos[k] = src[k];
    for (int k = t; k < NSUB; k += TPB) { s_n[k] = 0.0f; s_m[k] = 0.0f; }
    __syncthreads();

    const float cut2 = CUT_ADJ * CUT_ADJ;
    const int stride = ABLK_X * TPB;     // 37888

    // Balanced triangle: row u (len N-1-u) paired with row N-2-u (len u+1)
    for (int r = blockIdx.x * TPB + t; r < PB_SPACE; r += stride) {
        int u = r / NATOMS;
        int v = r - u * NATOMS;
        int i, j;
        int lim = NATOMS - 1 - u;
        if (v < lim) { i = u; j = u + 1 + v; }
        else         { i = NATOMS - 2 - u; if (i == u) continue; j = v; }

        float dx = s_pos[3 * j + 0] - s_pos[3 * i + 0];
        float dy = s_pos[3 * j + 1] - s_pos[3 * i + 1];
        float dz = s_pos[3 * j + 2] - s_pos[3 * i + 2];
        if (dx >= 10.0f) dx -= 20.0f; else if (dx < -10.0f) dx += 20.0f;
        if (dy >= 10.0f) dy -= 20.0f; else if (dy < -10.0f) dy += 20.0f;
        if (dz >= 10.0f) dz -= 20.0f; else if (dz < -10.0f) dz += 20.0f;

        float ds = dx * dx + dy * dy + dz * dz;
        if (ds >= cut2 || ds == 0.0f) continue;

        float d = sqrtf(ds);
        int s = (int)(d * INV_SUBW);
        if (s > NSUB - 1) s = NSUB - 1;          // fp edge guard
        float cs = ((float)s + 0.5f) * SUBW;
        atomicAdd(&s_n[s], 1.0f);
        atomicAdd(&s_m[s], d - cs);
    }
    __syncthreads();

    // non-atomic flush: every block overwrites its slot every run (no zeroing)
    const int blin = bat * ABLK_X + blockIdx.x;
    for (int k = t; k < NSUB; k += TPB) {
        g_pn[blin * NSUB + k] = s_n[k];
        g_pm[blin * NSUB + k] = s_m[k];
    }
}

// -------- Stage B: reduce partials, Gaussian reconstruction, finalize --------
__global__ void __launch_bounds__(TPB)
rdf_reduce_kernel(float* __restrict__ out, int out_size) {
    __shared__ float s_h[NBINS];
    __shared__ float s_cnt[NBINS];
    __shared__ float s_total;
    __shared__ int   s_last;

    const int t = threadIdx.x;
    const int slice   = blockIdx.x & (B_SLICES - 1);
    const int s_chunk = blockIdx.x >> 3;
    const int s = s_chunk * TPB + t;             // this thread's sub-bin

    if (t < NBINS) s_h[t] = 0.0f;
    __syncthreads();

    // sum this slice of per-block partials (coalesced across t)
    float n = 0.0f, m = 0.0f;
    #pragma unroll 4
    for (int b = slice; b < A_BLOCKS; b += B_SLICES) {
        n += g_pn[b * NSUB + s];
        m += g_pm[b * NSUB + s];
    }

    if (n != 0.0f || m != 0.0f) {
        float cs = ((float)s + 0.5f) * SUBW;
        int kc = __float2int_rn(cs * INV_GW);
        int k0 = kc - WIN2; if (k0 < 0) k0 = 0;
        int k1 = kc + WIN2; if (k1 > NBINS - 1) k1 = NBINS - 1;
        for (int k = k0; k <= k1; ++k) {
            float u = cs - (float)k * GW;
            float f = __expf(GCOEFF * u * u);
            // first-order Taylor: n*f(cs) + m*f'(cs),  f' = 2c*u*f
            atomicAdd(&s_h[k], f * (n + 2.0f * GCOEFF * u * m));
        }
    }
    __syncthreads();

    if (t < NBINS) g_bpart[blockIdx.x * NBINS + t] = s_h[t];
    __threadfence();
    __syncthreads();
    if (t == 0) {
        unsigned int old = atomicAdd(&g_done2, 1u);
        s_last = (old == B_BLOCKS - 1);
    }
    __syncthreads();
    if (!s_last) return;

    // ---- last block: final reduce + normalize ----
    __threadfence();
    if (t < NBINS) {
        float v = 0.0f;
        #pragma unroll 4
        for (int b = 0; b < B_BLOCKS; ++b) v += g_bpart[b * NBINS + t];
        s_cnt[t] = v;
    }
    __syncthreads();
    if (t == 0) {
        float sum = 0.0f;
        for (int k = 0; k < NBINS; ++k) sum += s_cnt[k];
        s_total = sum;
        g_done2 = 0;                      // reset for next graph replay
    }
    __syncthreads();

    const float pi43 = 4.0f * 3.14159265358979f / 3.0f;
    const float num  = (2.0f * CUT_ADJ) * (2.0f * CUT_ADJ) * (2.0f * CUT_ADJ);
    if (out_size >= 2 * NBINS + 1) {
        // layout: BINS[65] then rdf[64]
        if (t <= NBINS) out[t] = (float)t * BIN_W;
        if (t < NBINS) {
            float b0 = (float)t * BIN_W;
            float b1 = (float)(t + 1) * BIN_W;
            float vol = pi43 * (b1 * b1 * b1 - b0 * b0 * b0);
            out[NBINS + 1 + t] = (s_cnt[t] / s_total) * num / (2.0f * vol);
        }
    } else {
        if (t < NBINS && t < out_size) {
            float b0 = (float)t * BIN_W;
            float b1 = (float)(t + 1) * BIN_W;
            float vol = pi43 * (b1 * b1 * b1 - b0 * b0 * b0);
            out[t] = (s_cnt[t] / s_total) * num / (2.0f * vol);
        }
    }
}

extern "C" void kernel_launch(void* const* d_in, const int* in_sizes, int n_in,
                              void* d_out, int out_size) {
    const float* xyz = (const float*)d_in[0];
    float* out = (float*)d_out;
    dim3 gridA(ABLK_X, NBATCH);
    rdf_pairs_kernel<<<gridA, TPB>>>(xyz);
    rdf_reduce_kernel<<<B_BLOCKS, TPB>>>(out, out_size);
}

// round 4
// speedup vs baseline: 2.4691x; 2.4691x over previous
#include <cuda_runtime.h>
#include <math.h>

// ---- problem constants ----
#define NBATCH 4
#define NATOMS 600
#define HALFN  300
#define NBINS  64
#define BIN_W      0.1171875f            // 7.5/64 (exact fp32)
#define CUT_ADJ    7.734375f             // 7.5 + 2*BIN_W (exact)
#define GW         (7.5f / 63.0f)        // Gaussian offset spacing == width
#define GCOEFF     (-0.5f / (GW * GW))

// fine sub-histogram (single global copy, 16 KB -> L2 resident)
#define NSUB       2048
#define SUBW       (CUT_ADJ / (float)NSUB)
#define INV_SUBW   ((float)NSUB / CUT_ADJ)
#define WIN2       6                     // +-6 Gaussian widths: truncation ~ e^-18

#define ABLK_X     148
#define A_BLOCKS   (ABLK_X * NBATCH)     // 592
#define TPB        256
#define PB_SPACE   (HALFN * NATOMS)      // 180000 balanced-triangle slots/batch

// static device scratch (no cudaMalloc allowed); zero at module load,
// re-zeroed by the finalize block every call -> graph-replay deterministic
__device__ float        g_n[NSUB];
__device__ float        g_m[NSUB];
__device__ unsigned int g_done = 0;

__global__ void __launch_bounds__(TPB)
rdf_fused_kernel(const float* __restrict__ xyz, float* __restrict__ out, int out_size) {
    __shared__ float s_pos[NATOMS * 3];  // 7.2 KB
    __shared__ float s_n[NSUB];          // 8 KB
    __shared__ float s_m[NSUB];          // 8 KB
    __shared__ float s_cnt[NBINS];
    __shared__ float s_total;
    __shared__ int   s_last;

    const int t   = threadIdx.x;
    const int bat = blockIdx.y;

    const float* __restrict__ src = xyz + bat * NATOMS * 3;
    for (int k = t; k < NATOMS * 3; k += TPB) s_pos[k] = src[k];
    for (int k = t; k < NSUB; k += TPB) { s_n[k] = 0.0f; s_m[k] = 0.0f; }
    __syncthreads();

    const float cut2 = CUT_ADJ * CUT_ADJ;
    const int stride = ABLK_X * TPB;     // 37888

    // Balanced triangle: row u (len N-1-u) paired with row N-2-u (len u+1)
    for (int r = blockIdx.x * TPB + t; r < PB_SPACE; r += stride) {
        int u = r / NATOMS;
        int v = r - u * NATOMS;
        int i, j;
        int lim = NATOMS - 1 - u;
        if (v < lim) { i = u; j = u + 1 + v; }
        else         { i = NATOMS - 2 - u; if (i == u) continue; j = v; }

        float dx = s_pos[3 * j + 0] - s_pos[3 * i + 0];
        float dy = s_pos[3 * j + 1] - s_pos[3 * i + 1];
        float dz = s_pos[3 * j + 2] - s_pos[3 * i + 2];
        if (dx >= 10.0f) dx -= 20.0f; else if (dx < -10.0f) dx += 20.0f;
        if (dy >= 10.0f) dy -= 20.0f; else if (dy < -10.0f) dy += 20.0f;
        if (dz >= 10.0f) dz -= 20.0f; else if (dz < -10.0f) dz += 20.0f;

        float ds = dx * dx + dy * dy + dz * dz;
        if (ds >= cut2 || ds == 0.0f) continue;

        float d = sqrtf(ds);
        int s = (int)(d * INV_SUBW);
        if (s > NSUB - 1) s = NSUB - 1;
        float cs = ((float)s + 0.5f) * SUBW;
        atomicAdd(&s_n[s], 1.0f);
        atomicAdd(&s_m[s], d - cs);
    }
    __syncthreads();

    // flush to the single global sub-histogram (skip empty bins: ~halves REDG)
    for (int k = t; k < NSUB; k += TPB) {
        float vn = s_n[k], vm = s_m[k];
        if (vn != 0.0f) {
            atomicAdd(&g_n[k], vn);
            atomicAdd(&g_m[k], vm);
        }
    }
    __threadfence();
    __syncthreads();
    if (t == 0) {
        unsigned int old = atomicAdd(&g_done, 1u);
        s_last = (old == A_BLOCKS - 1);
    }
    __syncthreads();
    if (!s_last) return;

    // ================= last block: reconstruction + finalize =================
    __threadfence();

    // Each final bin k handled by 4 threads; thread covers a contiguous chunk
    // of the ~378-sub-bin window. Exp recurrence: e_{s+1}=e_s*t_s, t_{s+1}=t_s*q.
    {
        const int k   = t >> 2;          // 0..63
        const int seg = t & 3;
        const float ck = (float)k * GW;

        int s_lo = (int)ceilf((ck - WIN2 * GW) * INV_SUBW - 0.5f);
        int s_hi = (int)floorf((ck + WIN2 * GW) * INV_SUBW - 0.5f);
        if (s_lo < 0) s_lo = 0;
        if (s_hi > NSUB - 1) s_hi = NSUB - 1;
        int cnt = s_hi - s_lo + 1;
        int len = (cnt + 3) >> 2;
        int a = s_lo + seg * len;
        int b = a + len - 1; if (b > s_hi) b = s_hi;

        float acc = 0.0f;
        if (a <= b) {
            const float dlt = SUBW;
            float u = ((float)a + 0.5f) * SUBW - ck;       // signed offset
            float e = __expf(GCOEFF * u * u);
            float tt = __expf(GCOEFF * (2.0f * u * dlt + dlt * dlt));
            const float q = __expf(2.0f * GCOEFF * dlt * dlt);
            for (int s = a; s <= b; ++s) {
                float n = g_n[s];
                float m = g_m[s];
                // first-order Taylor: n*f + m*f', f' = 2c*u*f
                acc = fmaf(e, fmaf(2.0f * GCOEFF * u, m, n), acc);
                e *= tt;
                tt *= q;
                u += dlt;
            }
        }
        acc += __shfl_xor_sync(0xffffffffu, acc, 1);
        acc += __shfl_xor_sync(0xffffffffu, acc, 2);
        if (seg == 0) s_cnt[k] = acc;
    }
    __syncthreads();

    // zero globals for next graph replay (after all reads)
    for (int k = t; k < NSUB; k += TPB) { g_n[k] = 0.0f; g_m[k] = 0.0f; }
    if (t == 0) {
        float sum = 0.0f;
        for (int k = 0; k < NBINS; ++k) sum += s_cnt[k];
        s_total = sum;
        g_done = 0;
    }
    __syncthreads();

    const float pi43 = 4.0f * 3.14159265358979f / 3.0f;
    const float num  = (2.0f * CUT_ADJ) * (2.0f * CUT_ADJ) * (2.0f * CUT_ADJ);
    if (out_size >= 2 * NBINS + 1) {
        // layout: BINS[65] then rdf[64]
        if (t <= NBINS) out[t] = (float)t * BIN_W;
        if (t < NBINS) {
            float b0 = (float)t * BIN_W;
            float b1 = (float)(t + 1) * BIN_W;
            float vol = pi43 * (b1 * b1 * b1 - b0 * b0 * b0);
            out[NBINS + 1 + t] = (s_cnt[t] / s_total) * num / (2.0f * vol);
        }
    } else {
        if (t < NBINS && t < out_size) {
            float b0 = (float)t * BIN_W;
            float b1 = (float)(t + 1) * BIN_W;
            float vol = pi43 * (b1 * b1 * b1 - b0 * b0 * b0);
            out[t] = (s_cnt[t] / s_total) * num / (2.0f * vol);
        }
    }
}

extern "C" void kernel_launch(void* const* d_in, const int* in_sizes, int n_in,
                              void* d_out, int out_size) {
    const float* xyz = (const float*)d_in[0];
    float* out = (float*)d_out;
    dim3 grid(ABLK_X, NBATCH);
    rdf_fused_kernel<<<grid, TPB>>>(xyz, out, out_size);
}

// round 5
// speedup vs baseline: 2.9917x; 1.2117x over previous
#include <cuda_runtime.h>
#include <math.h>

// ---- problem constants ----
#define NBATCH 4
#define NATOMS 600
#define HALFN  300
#define NBINS  64
#define BIN_W      0.1171875f            // 7.5/64 (exact fp32)
#define CUT_ADJ    7.734375f             // 7.5 + 2*BIN_W (exact)
#define GW         (7.5f / 63.0f)        // Gaussian offset spacing == width
#define GCOEFF     (-0.5f / (GW * GW))

// fine sub-histogram (single global copy, 16 KB -> L2 resident)
#define NSUB       2048
#define SUBW       (CUT_ADJ / (float)NSUB)
#define INV_SUBW   ((float)NSUB / CUT_ADJ)
#define WIN2       6                     // +-6 Gaussian widths: truncation ~ e^-18

#define ABLK_X     148
#define A_BLOCKS   (ABLK_X * NBATCH)     // 592
#define TPB        256
#define PB_SPACE   (HALFN * NATOMS)      // 180000
#define STRIDE     (ABLK_X * TPB)        // 37888 = 63*600 + 88
#define STEP_U     63
#define STEP_V     88

// static device scratch (zero at load; re-zeroed by finalize block each call)
__device__ __align__(16) float g_n[NSUB];
__device__ __align__(16) float g_m[NSUB];
__device__ unsigned int g_done = 0;

__global__ void __launch_bounds__(TPB)
rdf_fused_kernel(const float* __restrict__ xyz, float* __restrict__ out, int out_size) {
    __shared__ float4 s_pos[NATOMS];     // 9.6 KB, padded for single LDS.128
    __shared__ float  s_n[NSUB];         // 8 KB
    __shared__ float  s_m[NSUB];         // 8 KB
    __shared__ float  s_cnt[NBINS];
    __shared__ float  s_total;
    __shared__ int    s_last;

    const int t   = threadIdx.x;
    const int bat = blockIdx.y;

    const float* __restrict__ src = xyz + bat * NATOMS * 3;
    for (int k = t; k < NATOMS; k += TPB) {
        const float* p = src + 3 * k;
        s_pos[k] = make_float4(p[0], p[1], p[2], 0.0f);
    }
    #pragma unroll
    for (int k = t; k < NSUB; k += TPB) { s_n[k] = 0.0f; s_m[k] = 0.0f; }
    __syncthreads();

    const float cut2 = CUT_ADJ * CUT_ADJ;

    // Balanced triangle: row u (len N-1-u) paired with row N-2-u (len u+1).
    // (u,v) maintained incrementally -> no per-iteration integer division.
    int r = blockIdx.x * TPB + t;
    int u = r / NATOMS;
    int v = r - u * NATOMS;
    while (r < PB_SPACE) {
        int i, j;
        bool valid = true;
        int lim = NATOMS - 1 - u;
        if (v < lim) { i = u; j = u + 1 + v; }
        else         { i = NATOMS - 2 - u; j = v; valid = (i != u); }

        if (valid) {
            float4 pi = s_pos[i];
            float4 pj = s_pos[j];
            float dx = pj.x - pi.x;
            float dy = pj.y - pi.y;
            float dz = pj.z - pi.z;
            // minimum-image: distance-equivalent branch-free wrap
            dx = fmaf(-20.0f, rintf(dx * 0.05f), dx);
            dy = fmaf(-20.0f, rintf(dy * 0.05f), dy);
            dz = fmaf(-20.0f, rintf(dz * 0.05f), dz);

            float ds = fmaf(dx, dx, fmaf(dy, dy, dz * dz));
            if (ds < cut2 && ds != 0.0f) {
                float d = sqrtf(ds);
                int s = (int)(d * INV_SUBW);
                if (s > NSUB - 1) s = NSUB - 1;
                float cs = ((float)s + 0.5f) * SUBW;
                atomicAdd(&s_n[s], 1.0f);
                atomicAdd(&s_m[s], d - cs);
            }
        }
        r += STRIDE;
        u += STEP_U;
        v += STEP_V;
        if (v >= NATOMS) { v -= NATOMS; u += 1; }
    }
    __syncthreads();

    // flush to the single global sub-histogram (skip empty bins)
    #pragma unroll
    for (int k = t; k < NSUB; k += TPB) {
        float vn = s_n[k];
        if (vn != 0.0f) {
            atomicAdd(&g_n[k], vn);
            atomicAdd(&g_m[k], s_m[k]);
        }
    }
    __threadfence();
    __syncthreads();
    if (t == 0) {
        unsigned int old = atomicAdd(&g_done, 1u);
        s_last = (old == A_BLOCKS - 1);
    }
    __syncthreads();
    if (!s_last) return;

    // ================= last block: reconstruction + finalize =================
    __threadfence();

    // Stage the global sub-histogram into SHARED first (coalesced, full MLP):
    // the window loop below then reads 29-cyc LDS instead of ~250-cyc L2.
    #pragma unroll
    for (int k = t; k < NSUB; k += TPB) { s_n[k] = g_n[k]; s_m[k] = g_m[k]; }
    __syncthreads();
    // zero globals for next graph replay (reads done)
    #pragma unroll
    for (int k = t; k < NSUB; k += TPB) { g_n[k] = 0.0f; g_m[k] = 0.0f; }

    {
        const int k   = t >> 2;          // final bin 0..63
        const int seg = t & 3;
        const float ck = (float)k * GW;

        int s_lo = (int)ceilf((ck - WIN2 * GW) * INV_SUBW - 0.5f);
        int s_hi = (int)floorf((ck + WIN2 * GW) * INV_SUBW - 0.5f);
        if (s_lo < 0) s_lo = 0;
        if (s_hi > NSUB - 1) s_hi = NSUB - 1;
        int cnt = s_hi - s_lo + 1;
        int len = (cnt + 3) >> 2;
        int a = s_lo + seg * len;
        int b = a + len - 1; if (b > s_hi) b = s_hi;

        float acc = 0.0f;
        if (a <= b) {
            const float dlt = SUBW;
            float uu = ((float)a + 0.5f) * SUBW - ck;   // signed offset
            float e  = __expf(GCOEFF * uu * uu);
            float tt = __expf(GCOEFF * (2.0f * uu * dlt + dlt * dlt));
            const float q = __expf(2.0f * GCOEFF * dlt * dlt);
            for (int s = a; s <= b; ++s) {
                float n = s_n[s];
                float m = s_m[s];
                // first-order Taylor: n*f + m*f', f' = 2c*u*f
                acc = fmaf(e, fmaf(2.0f * GCOEFF * uu, m, n), acc);
                e *= tt;
                tt *= q;
                uu += dlt;
            }
        }
        acc += __shfl_xor_sync(0xffffffffu, acc, 1);
        acc += __shfl_xor_sync(0xffffffffu, acc, 2);
        if (seg == 0) s_cnt[k] = acc;
    }
    __syncthreads();
    if (t == 0) {
        float sum = 0.0f;
        for (int k = 0; k < NBINS; ++k) sum += s_cnt[k];
        s_total = sum;
        g_done = 0;
    }
    __syncthreads();

    const float pi43 = 4.0f * 3.14159265358979f / 3.0f;
    const float num  = (2.0f * CUT_ADJ) * (2.0f * CUT_ADJ) * (2.0f * CUT_ADJ);
    if (out_size >= 2 * NBINS + 1) {
        // layout: BINS[65] then rdf[64]
        if (t <= NBINS) out[t] = (float)t * BIN_W;
        if (t < NBINS) {
            float b0 = (float)t * BIN_W;
            float b1 = (float)(t + 1) * BIN_W;
            float vol = pi43 * (b1 * b1 * b1 - b0 * b0 * b0);
            out[NBINS + 1 + t] = (s_cnt[t] / s_total) * num / (2.0f * vol);
        }
    } else {
        if (t < NBINS && t < out_size) {
            float b0 = (float)t * BIN_W;
            float b1 = (float)(t + 1) * BIN_W;
            float vol = pi43 * (b1 * b1 * b1 - b0 * b0 * b0);
            out[t] = (s_cnt[t] / s_total) * num / (2.0f * vol);
        }
    }
}

extern "C" void kernel_launch(void* const* d_in, const int* in_sizes, int n_in,
                              void* d_out, int out_size) {
    const float* xyz = (const float*)d_in[0];
    float* out = (float*)d_out;
    dim3 grid(ABLK_X, NBATCH);
    rdf_fused_kernel<<<grid, TPB>>>(xyz, out, out_size);
}

// round 6
// speedup vs baseline: 3.0372x; 1.0152x over previous
#include <cuda_runtime.h>
#include <math.h>

// ---- problem constants ----
#define NBATCH 4
#define NATOMS 600
#define HALFN  300
#define NBINS  64
#define BIN_W      0.1171875f            // 7.5/64 (exact fp32)
#define CUT_ADJ    7.734375f             // 7.5 + 2*BIN_W (exact)
#define GW         (7.5f / 63.0f)        // Gaussian offset spacing == width
#define GCOEFF     (-0.5f / (GW * GW))

// fine sub-histogram: 1024 bins, (count, moment) packed into one u64
#define NSUB       1024
#define SUBW       (CUT_ADJ / (float)NSUB)
#define INV_SUBW   ((float)NSUB / CUT_ADJ)
#define FIX        4194304.0f            // 2^22 fixed-point scale for the moment
#define INV_FIX    (1.0f / 4194304.0f)
#define MBIAS      32768                 // keeps low 32-bit half non-negative

// finalize window: fixed 192 sub-bins (~ +-6.1 Gaussian widths), 96-entry guards
#define PAD        96
#define SEG_LEN    48                    // 4 threads per final bin

#define ABLK_X     222
#define A_BLOCKS   (ABLK_X * NBATCH)     // 888 = 6 waves * 148 SMs
#define TPB        256
#define PB_SPACE   (HALFN * NATOMS)      // 180000
#define STRIDE     (ABLK_X * TPB)        // 56832 = 94*600 + 432
#define STEP_U     94
#define STEP_V     432

// static device scratch (zero at load; re-zeroed by finalize block each call)
__device__ unsigned long long g_pk[NSUB];
__device__ unsigned int      g_done = 0;

__global__ void __launch_bounds__(TPB)
rdf_fused_kernel(const float* __restrict__ xyz, float* __restrict__ out, int out_size) {
    __shared__ float4             s_pos[NATOMS];       // 9.6 KB
    __shared__ unsigned long long s_pk[NSUB];          // 8 KB packed (n,m)
    __shared__ float              s_nf[NSUB + 2 * PAD];// 4.75 KB (finalize)
    __shared__ float              s_mf[NSUB + 2 * PAD];
    __shared__ float              s_cnt[NBINS];
    __shared__ float              s_total;
    __shared__ int                s_last;

    const int t   = threadIdx.x;
    const int bat = blockIdx.y;

    const float* __restrict__ src = xyz + bat * NATOMS * 3;
    for (int k = t; k < NATOMS; k += TPB) {
        const float* p = src + 3 * k;
        s_pos[k] = make_float4(p[0], p[1], p[2], 0.0f);
    }
    #pragma unroll
    for (int k = t; k < NSUB; k += TPB) s_pk[k] = 0ull;
    __syncthreads();

    const float cut2 = CUT_ADJ * CUT_ADJ;

    // Balanced triangle: row u (len N-1-u) paired with row N-2-u (len u+1);
    // (u,v) maintained incrementally (no per-iteration division).
    int r = blockIdx.x * TPB + t;
    int u = r / NATOMS;
    int v = r - u * NATOMS;
    while (r < PB_SPACE) {
        int i, j;
        bool valid = true;
        int lim = NATOMS - 1 - u;
        if (v < lim) { i = u; j = u + 1 + v; }
        else         { i = NATOMS - 2 - u; j = v; valid = (i != u); }

        if (valid) {
            float4 pi = s_pos[i];
            float4 pj = s_pos[j];
            float dx = pj.x - pi.x;
            float dy = pj.y - pi.y;
            float dz = pj.z - pi.z;
            // minimum-image: distance-equivalent branch-free wrap
            dx = fmaf(-20.0f, rintf(dx * 0.05f), dx);
            dy = fmaf(-20.0f, rintf(dy * 0.05f), dy);
            dz = fmaf(-20.0f, rintf(dz * 0.05f), dz);
            float ds = fmaf(dx, dx, fmaf(dy, dy, dz * dz));
            if (ds < cut2 && ds != 0.0f) {
                float d = ds * rsqrtf(ds);               // single MUFU
                int s = (int)(d * INV_SUBW);
                if (s > NSUB - 1) s = NSUB - 1;
                float cs = ((float)s + 0.5f) * SUBW;
                int mq = __float2int_rn((d - cs) * FIX); // |mq| < 24K
                unsigned long long pk =
                    (1ull << 32) | (unsigned long long)(unsigned)(mq + MBIAS);
                atomicAdd(&s_pk[s], pk);                 // ONE shared atomic/pair
            }
        }
        r += STRIDE;
        u += STEP_U;
        v += STEP_V;
        if (v >= NATOMS) { v -= NATOMS; u += 1; }
    }
    __syncthreads();

    // flush non-empty bins to the single global packed histogram
    #pragma unroll
    for (int k = t; k < NSUB; k += TPB) {
        unsigned long long pv = s_pk[k];
        if (pv) atomicAdd(&g_pk[k], pv);
    }
    __threadfence();
    __syncthreads();
    if (t == 0) {
        unsigned int old = atomicAdd(&g_done, 1u);
        s_last = (old == A_BLOCKS - 1);
    }
    __syncthreads();
    if (!s_last) return;

    // ================= last block: reconstruction + finalize =================
    __threadfence();

    // zero guard-padded staging arrays, then unpack global histogram into them
    #pragma unroll
    for (int k = t; k < NSUB + 2 * PAD; k += TPB) { s_nf[k] = 0.0f; s_mf[k] = 0.0f; }
    __syncthreads();
    #pragma unroll
    for (int k = t; k < NSUB; k += TPB) {
        unsigned long long pv = g_pk[k];
        g_pk[k] = 0ull;                                  // reset for next replay
        float n = (float)(unsigned)(pv >> 32);
        float m = ((float)(int)((unsigned)pv - (unsigned)(pv >> 32) * MBIAS)) * INV_FIX;
        s_nf[PAD + k] = n;
        s_mf[PAD + k] = m;
    }
    __syncthreads();

    // each final bin k: 4 threads x 48 fixed-trip unrolled sub-bins (window
    // ~ +-6.1 Gaussian widths; guards are zero so no bounds checks needed)
    {
        const int k   = t >> 2;
        const int seg = t & 3;
        const float ck = (float)k * GW;
        const int s0 = __float2int_rn(ck * INV_SUBW) - 96 + seg * SEG_LEN;

        float acc = 0.0f;
        float u0 = ((float)s0 + 0.5f) * SUBW - ck;
        #pragma unroll
        for (int ii = 0; ii < SEG_LEN; ++ii) {
            float n = s_nf[PAD + s0 + ii];
            float m = s_mf[PAD + s0 + ii];
            float uu = u0 + (float)ii * SUBW;
            float f = __expf(GCOEFF * uu * uu);
            // first-order Taylor: n*f + m*f', f' = 2c*u*f
            acc = fmaf(f, fmaf(2.0f * GCOEFF * uu, m, n), acc);
        }
        acc += __shfl_xor_sync(0xffffffffu, acc, 1);
        acc += __shfl_xor_sync(0xffffffffu, acc, 2);
        if (seg == 0) s_cnt[k] = acc;
    }
    __syncthreads();
    if (t == 0) {
        float sum = 0.0f;
        for (int k = 0; k < NBINS; ++k) sum += s_cnt[k];
        s_total = sum;
        g_done = 0;
    }
    __syncthreads();

    const float pi43 = 4.0f * 3.14159265358979f / 3.0f;
    const float num  = (2.0f * CUT_ADJ) * (2.0f * CUT_ADJ) * (2.0f * CUT_ADJ);
    if (out_size >= 2 * NBINS + 1) {
        // layout: BINS[65] then rdf[64]
        if (t <= NBINS) out[t] = (float)t * BIN_W;
        if (t < NBINS) {
            float b0 = (float)t * BIN_W;
            float b1 = (float)(t + 1) * BIN_W;
            float vol = pi43 * (b1 * b1 * b1 - b0 * b0 * b0);
            out[NBINS + 1 + t] = (s_cnt[t] / s_total) * num / (2.0f * vol);
        }
    } else {
        if (t < NBINS && t < out_size) {
            float b0 = (float)t * BIN_W;
            float b1 = (float)(t + 1) * BIN_W;
            float vol = pi43 * (b1 * b1 * b1 - b0 * b0 * b0);
            out[t] = (s_cnt[t] / s_total) * num / (2.0f * vol);
        }
    }
}

extern "C" void kernel_launch(void* const* d_in, const int* in_sizes, int n_in,
                              void* d_out, int out_size) {
    const float* xyz = (const float*)d_in[0];
    float* out = (float*)d_out;
    dim3 grid(ABLK_X, NBATCH);
    rdf_fused_kernel<<<grid, TPB>>>(xyz, out, out_size);
}